// round 17
// baseline (speedup 1.0000x reference)
#include <cuda_runtime.h>
#include <cuda_bf16.h>
#include <cstdint>

#define BATCH 16384
#define KD    1024
#define NOUT  289
#define H1D   256
#define H2D   128

// ---------------------------------------------------------------------------
// Device scratch (zero-initialized at load; Bt pad rows 289..319 stay 0).
// ---------------------------------------------------------------------------
__device__ float         g_cbias[NOUT];
__device__ __nv_bfloat16 g_Bthi[320 * KD];
__device__ __nv_bfloat16 g_Btlo[320 * KD];
__device__ __nv_bfloat16 g_W2thi[H2D * H1D];
__device__ __nv_bfloat16 g_W2tlo[H2D * H1D];

// ---------------------------------------------------------------------------
// Helpers (base sm_103 PTX only: mma.sync / ldmatrix / cp.async)
// ---------------------------------------------------------------------------
static __device__ __forceinline__ uint32_t smem_u32(const void* p) {
    uint32_t a;
    asm("{ .reg .u64 t; cvta.to.shared.u64 t, %1; cvt.u32.u64 %0, t; }" : "=r"(a) : "l"(p));
    return a;
}
static __device__ __forceinline__ void cp16(uint32_t dst, const void* src) {
    asm volatile("cp.async.cg.shared.global [%0], [%1], 16;\n" :: "r"(dst), "l"(src));
}
#define CP_COMMIT() asm volatile("cp.async.commit_group;\n" ::: "memory")
#define CP_WAIT0()  asm volatile("cp.async.wait_group 0;\n" ::: "memory")

#define LDSM4(r0, r1, r2, r3, addr) \
    asm volatile("ldmatrix.sync.aligned.m8n8.x4.shared.b16 {%0,%1,%2,%3}, [%4];" \
                 : "=r"(r0), "=r"(r1), "=r"(r2), "=r"(r3) : "r"(addr))

#define MMA16816(c, a, b) \
    asm volatile("mma.sync.aligned.m16n8k16.row.col.f32.bf16.bf16.f32 " \
                 "{%0,%1,%2,%3},{%4,%5,%6,%7},{%8,%9},{%0,%1,%2,%3};" \
                 : "+f"((c)[0]), "+f"((c)[1]), "+f"((c)[2]), "+f"((c)[3]) \
                 : "r"((a)[0]), "r"((a)[1]), "r"((a)[2]), "r"((a)[3]), \
                   "r"((b)[0]), "r"((b)[1]))

#define SWZ(x)   ((x) ^ (((x) >> 3) & 0x70))   // 128B-row swizzle

static __device__ __forceinline__ void split2(float v, __nv_bfloat16& h, __nv_bfloat16& l) {
    h = __float2bfloat16(v);
    l = __float2bfloat16(v - __bfloat162float(h));
}
static __device__ __forceinline__ uint32_t pack_bf2(__nv_bfloat16 a, __nv_bfloat16 b) {
    __nv_bfloat162 p; p.x = a; p.y = b;
    return *reinterpret_cast<uint32_t*>(&p);
}

// ---------------------------------------------------------------------------
// K0: merged precompute, ONE launch, one wave (49.7KB smem -> 4 blocks/SM).
//   blocks [0,128):   combine GEMM, 32x64 tile, half-K (128) strips, 2 phases
//   blocks [128,136): cbias[0:256] — coalesced c, 8 warps split j, smem reduce
//   blocks [136,...): ms/us/add rows of Bt, cbias[256:289], W2t split
// ---------------------------------------------------------------------------
#define KH 128
#define PRE_SMEM ((KH * 33 + KH * 64) * 4)     // 49664 bytes

__global__ __launch_bounds__(256) void k_pre(
    const float* __restrict__ Wm, const float* __restrict__ bm,
    const float* __restrict__ Wu, const float* __restrict__ bu,
    const float* __restrict__ W1, const float* __restrict__ b1,
    const float* __restrict__ W2)
{
    extern __shared__ float dsm[];
    __shared__ float red[8][32];
    int bid = blockIdx.x;
    int tid = threadIdx.x;

    if (bid < 128) {
        // ---- combine GEMM: Bt[n, kglob] = (Wm|Wu)[kglob, :256] @ W1half ----
        int z   = bid >> 6;                   // tower
        int rem = bid & 63;                   // 16 mblk x 4 nblk
        const float* A  = (z == 0) ? Wm : Wu;
        const float* Bw = (z == 0) ? W1 : (W1 + 256 * 256);
        int koff        = (z == 0) ? 0  : 512;
        const int lda = 257, ldb = 256;

        int m0 = (rem >> 2) * 32, n0 = (rem & 3) * 64;
        float* As = dsm;                      // [KH k][33 m-pad]
        float* Bs = dsm + KH * 33;            // [KH k][64 n]
        int tx = tid & 15, ty = tid >> 4;     // m = ty*2+i, n = tx*4+j
        float acc[2][4] = {};

        #pragma unroll 1
        for (int h = 0; h < 2; h++) {
            int k0 = h * KH;
            // A half-strip: threads split (k, row-half); 16 LDGs in flight.
            int kl = tid & 127;
            int rh = (tid >> 7) * 16;
            #pragma unroll
            for (int r = 0; r < 16; r++)
                As[kl * 33 + rh + r] = A[(m0 + rh + r) * lda + k0 + kl];
            // B half-strip: 128 k x 64 n, float4 coalesced.
            #pragma unroll
            for (int i = 0; i < 8; i++) {
                int f = i * 256 + tid;
                int k = f >> 4, nq = (f & 15) * 4;
                float4 v = *reinterpret_cast<const float4*>(Bw + (k0 + k) * ldb + n0 + nq);
                *reinterpret_cast<float4*>(&Bs[k * 64 + nq]) = v;
            }
            __syncthreads();
            #pragma unroll 8
            for (int k = 0; k < KH; k++) {
                float a0 = As[k * 33 + ty * 2];
                float a1 = As[k * 33 + ty * 2 + 1];
                float4 b = *reinterpret_cast<const float4*>(&Bs[k * 64 + tx * 4]);
                acc[0][0] += a0 * b.x; acc[0][1] += a0 * b.y;
                acc[0][2] += a0 * b.z; acc[0][3] += a0 * b.w;
                acc[1][0] += a1 * b.x; acc[1][1] += a1 * b.y;
                acc[1][2] += a1 * b.z; acc[1][3] += a1 * b.w;
            }
            if (h == 0) __syncthreads();
        }
        #pragma unroll
        for (int i = 0; i < 2; i++)
            #pragma unroll
            for (int j = 0; j < 4; j++) {
                int kg = koff + m0 + ty * 2 + i;
                int nr = n0 + tx * 4 + j;
                __nv_bfloat16 h, l;
                split2(acc[i][j], h, l);
                g_Bthi[(size_t)nr * KD + kg] = h;
                g_Btlo[(size_t)nr * KD + kg] = l;
            }
        return;
    }

    if (bid < 136) {
        // ---- cbias[0:256]: lanes = 32 coalesced c, 8 warps split j ----
        int cl = tid & 31, jp = tid >> 5;
        int c = (bid - 128) * 32 + cl;
        float p = 0.f;
        int j0 = jp * 64;
        #pragma unroll 16
        for (int i = 0; i < 64; i++) {
            int j = j0 + i;
            float bv = (j < 256) ? bm[j] : bu[j - 256];
            p += bv * W1[j * 256 + c];
        }
        red[jp][cl] = p;
        __syncthreads();
        if (jp == 0) {
            float s = b1[c];
            #pragma unroll
            for (int q = 0; q < 8; q++) s += red[q][cl];
            g_cbias[c] = s;
        }
        return;
    }

    // ---- rest ----
    int t = (bid - 136) * 256 + tid;
    if (t < KD * 16) {
        int k = t >> 4, d = t & 15;
        float s = 0.f;
        __nv_bfloat16 h, l;
        if (k < 512) {
            #pragma unroll
            for (int i = 0; i < 16; i++) s += Wm[k * 257 + i * 16 + d];
            split2(s, h, l);
            g_Bthi[(size_t)(256 + d) * KD + k] = h;
            g_Btlo[(size_t)(256 + d) * KD + k] = l;
            if (d == 0) {
                split2(Wm[k * 257 + 256], h, l);
                g_Bthi[(size_t)288 * KD + k] = h;
                g_Btlo[(size_t)288 * KD + k] = l;
            }
        } else {
            int ku = k - 512;
            #pragma unroll
            for (int i = 0; i < 16; i++) s += Wu[ku * 257 + i * 16 + d];
            split2(s, h, l);
            g_Bthi[(size_t)(272 + d) * KD + k] = h;
            g_Btlo[(size_t)(272 + d) * KD + k] = l;
            if (d == 0) {
                split2(Wu[ku * 257 + 256], h, l);
                g_Bthi[(size_t)288 * KD + k] = h;
                g_Btlo[(size_t)288 * KD + k] = l;
            }
        }
        return;
    }
    int c = t - KD * 16;
    if (c < 33) {
        int cc = 256 + c;
        float v;
        if (cc < 272) {
            int d = cc - 256; v = 0.f;
            #pragma unroll
            for (int i = 0; i < 16; i++) v += bm[i * 16 + d];
        } else if (cc < 288) {
            int d = cc - 272; v = 0.f;
            #pragma unroll
            for (int i = 0; i < 16; i++) v += bu[i * 16 + d];
        } else {
            v = bm[256] + bu[256];
        }
        g_cbias[cc] = v;
        return;
    }
    int j = c - 33;
    if (j < H2D * H1D) {
        int r = j >> 8, cc = j & 255;        // W2t[r][cc] = W2[cc][r]
        __nv_bfloat16 h, l;
        split2(W2[cc * H2D + r], h, l);
        g_W2thi[j] = h; g_W2tlo[j] = l;
    }
}

// ---------------------------------------------------------------------------
// K1: FUSED main + tail.
// Phase 1 (main): C[16384,320] = A[16384,1024 fp32] (x) Bt(hi/lo)^T, 3 terms,
//   128 CTAs, 512 thr (16 warps 4Mx4N, warp 32x80), CK=64, 2-stage.
// Phase 2 (tail, same CTA): h1(128x256) held in SMEM as bf16 hi/lo; W2t hi/lo
//   streamed via cp.async; 128x128x768 GEMM (warp 32x32); relu·W3 + FM + out.
// ---------------------------------------------------------------------------
#define CK         64
#define NCHUNK     16
#define AHI_OFF    0
#define ALO_OFF    16384
#define BHI_OFF    32768
#define BLO_OFF    73728
#define MAIN_STAGE 114688                     // 16+16+40+40 KB
#define SMEM_MAIN  (2 * MAIN_STAGE)           // 224 KB

// Tail overlay offsets (valid after main loop's final sync):
#define TH_HI   0                             // 4 chunks x 16KB = 64KB
#define TH_LO   65536                         // 64KB
#define TW2     131072                        // 2 bufs x 32KB (hi 16K + lo 16K)
#define TMSUS   196608                        // 128 rows x 36 floats = 18KB
#define TB2     215040                        // 128 floats
#define TW3     215552                        // 128 floats
#define TPS     216064                        // 128 x 4 floats

static __device__ __forceinline__ void ldg_a(float4* p, int ch, int m0, int t,
                                             const float* __restrict__ mv,
                                             const float* __restrict__ uv)
{
    int kc = ch * CK;
    const float* base = (kc < 512) ? (mv + kc) : (uv + kc - 512);
    #pragma unroll
    for (int l = 0; l < 4; l++) {
        int f = t + l * 512;
        int row = f >> 4, q = f & 15;
        p[l] = *reinterpret_cast<const float4*>(base + (size_t)(m0 + row) * 512 + q * 4);
    }
}

static __device__ __forceinline__ void sts_a(const float4* p, uint32_t stg, int t)
{
    #pragma unroll
    for (int l = 0; l < 4; l++) {
        int f = t + l * 512;
        int row = f >> 4, q = f & 15;
        __nv_bfloat16 h0, l0, h1, l1, h2, l2, h3, l3;
        split2(p[l].x, h0, l0); split2(p[l].y, h1, l1);
        split2(p[l].z, h2, l2); split2(p[l].w, h3, l3);
        uint32_t hi0 = pack_bf2(h0, h1), hi1 = pack_bf2(h2, h3);
        uint32_t lo0 = pack_bf2(l0, l1), lo1 = pack_bf2(l2, l3);
        uint32_t off = SWZ(row * 128 + q * 8);
        asm volatile("st.shared.v2.b32 [%0], {%1,%2};"
                     :: "r"(stg + AHI_OFF + off), "r"(hi0), "r"(hi1) : "memory");
        asm volatile("st.shared.v2.b32 [%0], {%1,%2};"
                     :: "r"(stg + ALO_OFF + off), "r"(lo0), "r"(lo1) : "memory");
    }
}

static __device__ __forceinline__ void cp_b(uint32_t stg, int ch, int t)
{
    int kc = ch * CK;
    #pragma unroll
    for (int l = 0; l < 10; l++) {
        int f = t + l * 512;                  // 0..5119: 2560 hi + 2560 lo units
        int lobuf = f >= 2560;
        int fr = lobuf ? f - 2560 : f;
        int row = fr >> 3, u = fr & 7;
        const __nv_bfloat16* src = (lobuf ? g_Btlo : g_Bthi) + (size_t)row * KD + kc + u * 8;
        cp16(stg + (lobuf ? BLO_OFF : BHI_OFF) + SWZ(row * 128 + u * 16), src);
    }
}

static __device__ __forceinline__ void cp_w2(uint32_t sb, int buf, int ch, int t)
{
    int kc = ch * 64;
    #pragma unroll
    for (int l = 0; l < 4; l++) {
        int f = t + l * 512;                  // 0..2047: 1024 hi + 1024 lo
        int lo = f >= 1024;
        int fr = lo ? f - 1024 : f;
        int row = fr >> 3, u = fr & 7;
        const __nv_bfloat16* src = (lo ? g_W2tlo : g_W2thi) + row * H1D + kc + u * 8;
        cp16(sb + TW2 + buf * 32768 + (lo ? 16384 : 0) + SWZ(row * 128 + u * 16), src);
    }
}

static __device__ __forceinline__ void chunk_ks(uint32_t stg, int ks,
                                                int wm, int wn,
                                                int a_row, int a_koff,
                                                int b_row, int b_koff,
                                                float c[2][10][4])
{
    uint32_t ahi[2][4], alo[2][4];
    #pragma unroll
    for (int mt = 0; mt < 2; mt++) {
        uint32_t ra = SWZ((wm * 32 + mt * 16 + a_row) * 128 + ks * 32 + a_koff);
        LDSM4(ahi[mt][0], ahi[mt][1], ahi[mt][2], ahi[mt][3], stg + AHI_OFF + ra);
        LDSM4(alo[mt][0], alo[mt][1], alo[mt][2], alo[mt][3], stg + ALO_OFF + ra);
    }
    #pragma unroll
    for (int jp = 0; jp < 5; jp++) {
        uint32_t rb = SWZ((wn * 80 + jp * 16 + b_row) * 128 + ks * 32 + b_koff);
        uint32_t b0[2], b1[2];
        LDSM4(b0[0], b0[1], b1[0], b1[1], stg + BHI_OFF + rb);   // Bhi
        #pragma unroll
        for (int mt = 0; mt < 2; mt++) {
            MMA16816(c[mt][2 * jp],     ahi[mt], b0);
            MMA16816(c[mt][2 * jp + 1], ahi[mt], b1);
            MMA16816(c[mt][2 * jp],     alo[mt], b0);
            MMA16816(c[mt][2 * jp + 1], alo[mt], b1);
        }
        LDSM4(b0[0], b0[1], b1[0], b1[1], stg + BLO_OFF + rb);   // Blo
        #pragma unroll
        for (int mt = 0; mt < 2; mt++) {
            MMA16816(c[mt][2 * jp],     ahi[mt], b0);
            MMA16816(c[mt][2 * jp + 1], ahi[mt], b1);
        }
    }
}

__global__ __launch_bounds__(512, 1) void k_mma_main(
    const float* __restrict__ mv, const float* __restrict__ uv,
    const float* __restrict__ b2, const float* __restrict__ W3,
    const float* __restrict__ b3, float* __restrict__ out)
{
    extern __shared__ char smem[];
    uint32_t sb = smem_u32(smem);
    int t = threadIdx.x;
    int lane = t & 31, wid = t >> 5;
    int wm = wid & 3, wn = wid >> 2;          // 4M x 4N warps
    int m0 = blockIdx.x * 128;

    float c[2][10][4];
    #pragma unroll
    for (int i = 0; i < 2; i++)
        #pragma unroll
        for (int j = 0; j < 10; j++)
            #pragma unroll
            for (int q = 0; q < 4; q++) c[i][j][q] = 0.f;

    int a_row  = (lane & 15);
    int a_koff = (lane >> 4) * 16;
    int b_row  = ((lane >> 4) & 1) * 8 + (lane & 7);
    int b_koff = ((lane >> 3) & 1) * 16;

    // ---------------- Phase 1: main GEMM ----------------
    {
        float4 q0[4];
        ldg_a(q0, 0, m0, t, mv, uv);
        cp_b(sb, 0, t); CP_COMMIT();
        sts_a(q0, sb, t);
    }

    float4 pf[4];
    #pragma unroll 1
    for (int ic = 0; ic < NCHUNK; ic++) {
        bool pfv = (ic + 1 < NCHUNK);
        if (pfv) ldg_a(pf, ic + 1, m0, t, mv, uv);
        CP_WAIT0();
        __syncthreads();
        uint32_t nstg = sb + ((ic + 1) & 1) * MAIN_STAGE;
        if (pfv) cp_b(nstg, ic + 1, t);
        CP_COMMIT();

        uint32_t stg = sb + (ic & 1) * MAIN_STAGE;
        chunk_ks(stg, 0, wm, wn, a_row, a_koff, b_row, b_koff, c);
        chunk_ks(stg, 1, wm, wn, a_row, a_koff, b_row, b_koff, c);
        if (pfv) sts_a(pf, nstg, t);
        chunk_ks(stg, 2, wm, wn, a_row, a_koff, b_row, b_koff, c);
        chunk_ks(stg, 3, wm, wn, a_row, a_koff, b_row, b_koff, c);
    }

    __syncthreads();   // all warps done reading stage smem -> overlay is safe

    // ---------------- Epilogue: bias+relu, H -> SMEM, ms/us/add -> SMEM ----
    float b2v = 0.f, w3v = 0.f;
    if (t < 128) { b2v = b2[t]; w3v = W3[t]; }   // prefetch (LDG latency hidden)

    #pragma unroll
    for (int mt = 0; mt < 2; mt++) {
        #pragma unroll
        for (int half = 0; half < 2; half++) {
            int r = wm * 32 + mt * 16 + (lane >> 2) + half * 8;  // CTA-local row
            #pragma unroll
            for (int j = 0; j < 10; j++) {
                int n = wn * 80 + j * 8 + (lane & 3) * 2;
                float v0 = c[mt][j][half * 2 + 0] + g_cbias[n < NOUT ? n : 0];
                float v1 = c[mt][j][half * 2 + 1] + g_cbias[(n + 1) < NOUT ? (n + 1) : 0];
                if (n < 256) {
                    v0 = fmaxf(v0, 0.f); v1 = fmaxf(v1, 0.f);
                    __nv_bfloat16 h0, l0, h1, l1;
                    split2(v0, h0, l0); split2(v1, h1, l1);
                    uint32_t off = (n >> 6) * 16384 + SWZ(r * 128 + (n & 63) * 2);
                    *reinterpret_cast<uint32_t*>(smem + TH_HI + off) = pack_bf2(h0, h1);
                    *reinterpret_cast<uint32_t*>(smem + TH_LO + off) = pack_bf2(l0, l1);
                } else {
                    float* msus = reinterpret_cast<float*>(smem + TMSUS) + r * 36;
                    #pragma unroll
                    for (int e = 0; e < 2; e++) {
                        int ne = n + e;
                        float ve = e ? v1 : v0;
                        if (ne < 272)       msus[ne - 256] = ve;        // ms
                        else if (ne < 288)  msus[16 + ne - 272] = ve;   // us
                        else if (ne == 288) msus[32] = ve;              // add
                    }
                }
            }
        }
    }
    if (t < 128) {
        reinterpret_cast<float*>(smem + TB2)[t] = b2v;
        reinterpret_cast<float*>(smem + TW3)[t] = w3v;
    }
    cp_w2(sb, 0, 0, t); CP_COMMIT();

    // ---------------- Phase 2: tail GEMM (warp = 32 rows x 32 cols) --------
    float a2[2][4][4];
    #pragma unroll
    for (int i = 0; i < 2; i++)
        #pragma unroll
        for (int j = 0; j < 4; j++)
            #pragma unroll
            for (int q = 0; q < 4; q++) a2[i][j][q] = 0.f;

    #pragma unroll 1
    for (int ch = 0; ch < 4; ch++) {
        CP_WAIT0();
        __syncthreads();            // W2(ch) ready; prior readers of other buf done
        if (ch + 1 < 4) cp_w2(sb, (ch + 1) & 1, ch + 1, t);
        CP_COMMIT();

        uint32_t hh  = sb + TH_HI + ch * 16384;
        uint32_t hl  = sb + TH_LO + ch * 16384;
        uint32_t w2h = sb + TW2 + (ch & 1) * 32768;
        uint32_t w2l = w2h + 16384;
        #pragma unroll
        for (int ks = 0; ks < 4; ks++) {
            uint32_t ahi[2][4], alo[2][4];
            #pragma unroll
            for (int mt = 0; mt < 2; mt++) {
                uint32_t ra = SWZ((wm * 32 + mt * 16 + a_row) * 128 + ks * 32 + a_koff);
                LDSM4(ahi[mt][0], ahi[mt][1], ahi[mt][2], ahi[mt][3], hh + ra);
                LDSM4(alo[mt][0], alo[mt][1], alo[mt][2], alo[mt][3], hl + ra);
            }
            uint32_t bh[4][2], bl[4][2];
            #pragma unroll
            for (int jp = 0; jp < 2; jp++) {
                uint32_t rb = SWZ((wn * 32 + jp * 16 + b_row) * 128 + ks * 32 + b_koff);
                LDSM4(bh[2 * jp][0], bh[2 * jp][1], bh[2 * jp + 1][0], bh[2 * jp + 1][1], w2h + rb);
                LDSM4(bl[2 * jp][0], bl[2 * jp][1], bl[2 * jp + 1][0], bl[2 * jp + 1][1], w2l + rb);
            }
            #pragma unroll
            for (int mt = 0; mt < 2; mt++)
                #pragma unroll
                for (int j = 0; j < 4; j++) {
                    MMA16816(a2[mt][j], ahi[mt], bh[j]);
                    MMA16816(a2[mt][j], alo[mt], bh[j]);
                    MMA16816(a2[mt][j], ahi[mt], bl[j]);
                }
        }
    }

    // relu(+b2)·w3 over this warp's 32 cols, lane-reduce, cross-warp via smem.
    const float* b2s = reinterpret_cast<const float*>(smem + TB2);
    const float* w3s = reinterpret_cast<const float*>(smem + TW3);
    float* ps = reinterpret_cast<float*>(smem + TPS);
    #pragma unroll
    for (int mt = 0; mt < 2; mt++) {
        float p0 = 0.f, p1 = 0.f;
        #pragma unroll
        for (int j = 0; j < 4; j++) {
            int n = wn * 32 + j * 8 + (lane & 3) * 2;
            p0 += fmaxf(a2[mt][j][0] + b2s[n],     0.f) * w3s[n];
            p0 += fmaxf(a2[mt][j][1] + b2s[n + 1], 0.f) * w3s[n + 1];
            p1 += fmaxf(a2[mt][j][2] + b2s[n],     0.f) * w3s[n];
            p1 += fmaxf(a2[mt][j][3] + b2s[n + 1], 0.f) * w3s[n + 1];
        }
        p0 += __shfl_xor_sync(0xFFFFFFFF, p0, 1);
        p0 += __shfl_xor_sync(0xFFFFFFFF, p0, 2);
        p1 += __shfl_xor_sync(0xFFFFFFFF, p1, 1);
        p1 += __shfl_xor_sync(0xFFFFFFFF, p1, 2);
        if ((lane & 3) == 0) {
            int r0 = wm * 32 + mt * 16 + (lane >> 2);
            ps[r0 * 4 + wn]       = p0;
            ps[(r0 + 8) * 4 + wn] = p1;
        }
    }
    __syncthreads();

    if (t < 128) {
        const float* msus = reinterpret_cast<const float*>(smem + TMSUS) + t * 36;
        float s = b3[0] + msus[32] + ps[t * 4] + ps[t * 4 + 1] + ps[t * 4 + 2] + ps[t * 4 + 3];
        #pragma unroll
        for (int i = 0; i < 16; i++) s += msus[i] * msus[16 + i];
        out[m0 + t] = s;
    }
}

// ---------------------------------------------------------------------------
extern "C" void kernel_launch(void* const* d_in, const int* in_sizes, int n_in,
                              void* d_out, int out_size)
{
    const float* mv = (const float*)d_in[0];
    const float* uv = (const float*)d_in[1];
    const float* Wm = (const float*)d_in[2];
    const float* bm = (const float*)d_in[3];
    const float* Wu = (const float*)d_in[4];
    const float* bu = (const float*)d_in[5];
    const float* W1 = (const float*)d_in[6];
    const float* b1 = (const float*)d_in[7];
    const float* W2 = (const float*)d_in[8];
    const float* b2 = (const float*)d_in[9];
    const float* W3 = (const float*)d_in[10];
    const float* b3 = (const float*)d_in[11];
    float* out = (float*)d_out;

    cudaFuncSetAttribute(k_pre,      cudaFuncAttributeMaxDynamicSharedMemorySize, PRE_SMEM);
    cudaFuncSetAttribute(k_mma_main, cudaFuncAttributeMaxDynamicSharedMemorySize, SMEM_MAIN);

    // Merged precompute: 128 combine + 8 bias + 193 rest blocks, ONE wave
    // (49.7KB smem -> 4 blocks/SM -> 592 slots >= 329 blocks).
    const int PRE_BLKS = 136 + (KD * 16 + 33 + H2D * H1D + 255) / 256;
    k_pre<<<PRE_BLKS, 256, PRE_SMEM>>>(Wm, bm, Wu, bu, W1, b1, W2);

    // Fused main + tail GEMM, one wave of 128 CTAs.
    k_mma_main<<<BATCH / 128, 512, SMEM_MAIN>>>(mv, uv, b2, W3, b3, out);
}